// round 2
// baseline (speedup 1.0000x reference)
#include <cuda_runtime.h>
#include <cuda_bf16.h>
#include <cstdint>

// Problem constants
#define NB   64
#define TT   1024
#define EE   256
#define HH   128
#define G3   384          // 3*H
#define GALL 768          // both directions
#define MROWS (NB*TT)     // 65536
#define BOTTLE 32

// ---------------- scratch (static device globals; no runtime alloc) ----------
__device__ float g_wcomb[GALL * EE];          // [768][256] combined W_ih
__device__ float g_bcomb[GALL];               // [768] combined b_ih
__device__ float g_gx[(size_t)MROWS * GALL];  // [65536][768] input gate preacts
__device__ float g_hsf[(size_t)MROWS * HH];   // forward hidden states  [m][u]
__device__ float g_hsb[(size_t)MROWS * HH];   // backward hidden states [m][u]

// ---------------- helpers ----------------------------------------------------
__device__ __forceinline__ float sigm_f(float x) {
    return __fdividef(1.f, 1.f + __expf(-x));
}
__device__ __forceinline__ float tanh_f(float x) {
    return __fdividef(2.f, 1.f + __expf(-2.f * x)) - 1.f;
}
__device__ __forceinline__ unsigned long long pack2(float lo, float hi) {
    unsigned long long r;
    asm("mov.b64 %0, {%1,%2};" : "=l"(r) : "f"(lo), "f"(hi));
    return r;
}
__device__ __forceinline__ float2 unpack2(unsigned long long v) {
    float2 f;
    asm("mov.b64 {%0,%1}, %2;" : "=f"(f.x), "=f"(f.y) : "l"(v));
    return f;
}
__device__ __forceinline__ unsigned long long fma2(unsigned long long a,
                                                   unsigned long long b,
                                                   unsigned long long c) {
    unsigned long long d;
    asm("fma.rn.f32x2 %0, %1, %2, %3;" : "=l"(d) : "l"(a), "l"(b), "l"(c));
    return d;
}
__device__ __forceinline__ uint32_t cvt_tf32(float f) {
    uint32_t r;
    asm("cvt.rna.tf32.f32 %0, %1;" : "=r"(r) : "f"(f));
    return r;
}
__device__ __forceinline__ void mma_tf32(float* c, const uint32_t* a, const uint32_t* b) {
    asm volatile(
        "mma.sync.aligned.m16n8k8.row.col.f32.tf32.tf32.f32 "
        "{%0,%1,%2,%3}, {%4,%5,%6,%7}, {%8,%9}, {%0,%1,%2,%3};"
        : "+f"(c[0]), "+f"(c[1]), "+f"(c[2]), "+f"(c[3])
        : "r"(a[0]), "r"(a[1]), "r"(a[2]), "r"(a[3]), "r"(b[0]), "r"(b[1]));
}

// ---------------- kernel 0: pack input weights/biases ------------------------
__global__ void pack_weights(const float* __restrict__ w_ih_f,
                             const float* __restrict__ b_ih_f,
                             const float* __restrict__ w_ih_b,
                             const float* __restrict__ b_ih_b) {
    int i = blockIdx.x * blockDim.x + threadIdx.x;
    if (i < GALL * EE) {
        int g = i / EE;
        g_wcomb[i] = (g < G3) ? w_ih_f[i] : w_ih_b[i - G3 * EE];
    }
    if (i < GALL) {
        g_bcomb[i] = (i < G3) ? b_ih_f[i] : b_ih_b[i - G3];
    }
}

// ---------------- kernel 1: gx GEMM via tf32 mma.sync -------------------------
// C[65536,768] = X[65536,256] * Wcomb^T[256,768];  tiles 128x128x32, 8 warps.
#define GBM 128
#define GBN 128
#define GBK 32
#define ASTRIDE 136
__global__ __launch_bounds__(256) void gemm_gx_mma(const float* __restrict__ X) {
    __shared__ uint32_t As[GBK][ASTRIDE];   // As[k][m] (tf32 bits)
    __shared__ uint32_t Bs[GBK][ASTRIDE];   // Bs[k][n]

    const int tid = threadIdx.x;
    const int lane = tid & 31;
    const int warp = tid >> 5;
    const int wm = warp & 3;      // 0..3 -> 32-row slab
    const int wn = warp >> 2;     // 0..1 -> 64-col slab
    const int m0 = blockIdx.x * GBM;
    const int n0 = blockIdx.y * GBN;

    float c[2][8][4];
#pragma unroll
    for (int mt = 0; mt < 2; mt++)
#pragma unroll
        for (int nt = 0; nt < 8; nt++)
#pragma unroll
            for (int q = 0; q < 4; q++) c[mt][nt][q] = 0.f;

    for (int k0 = 0; k0 < EE; k0 += GBK) {
        // A tile: X[m0+r][k0+c], stored transposed As[k][m]
#pragma unroll
        for (int l = 0; l < 4; l++) {
            int idx = tid + l * 256;       // 0..1023
            int r = idx >> 3;
            int c4 = idx & 7;
            float4 v = *reinterpret_cast<const float4*>(
                X + (size_t)(m0 + r) * EE + k0 + c4 * 4);
            As[c4 * 4 + 0][r] = cvt_tf32(v.x);
            As[c4 * 4 + 1][r] = cvt_tf32(v.y);
            As[c4 * 4 + 2][r] = cvt_tf32(v.z);
            As[c4 * 4 + 3][r] = cvt_tf32(v.w);
        }
        // B tile: wcomb[n0+r][k0+c] -> Bs[k][n]
#pragma unroll
        for (int l = 0; l < 4; l++) {
            int idx = tid + l * 256;
            int r = idx >> 3;
            int c4 = idx & 7;
            float4 v = *reinterpret_cast<const float4*>(
                g_wcomb + (size_t)(n0 + r) * EE + k0 + c4 * 4);
            Bs[c4 * 4 + 0][r] = cvt_tf32(v.x);
            Bs[c4 * 4 + 1][r] = cvt_tf32(v.y);
            Bs[c4 * 4 + 2][r] = cvt_tf32(v.z);
            Bs[c4 * 4 + 3][r] = cvt_tf32(v.w);
        }
        __syncthreads();

#pragma unroll
        for (int kt = 0; kt < 4; kt++) {
            const int kb = kt * 8;
            uint32_t a[2][4];
            uint32_t b[8][2];
            const int kc = kb + (lane & 3);
#pragma unroll
            for (int mt = 0; mt < 2; mt++) {
                int m = wm * 32 + mt * 16 + (lane >> 2);
                a[mt][0] = As[kc][m];
                a[mt][1] = As[kc][m + 8];
                a[mt][2] = As[kc + 4][m];
                a[mt][3] = As[kc + 4][m + 8];
            }
#pragma unroll
            for (int nt = 0; nt < 8; nt++) {
                int n = wn * 64 + nt * 8 + (lane >> 2);
                b[nt][0] = Bs[kc][n];
                b[nt][1] = Bs[kc + 4][n];
            }
#pragma unroll
            for (int mt = 0; mt < 2; mt++)
#pragma unroll
                for (int nt = 0; nt < 8; nt++) mma_tf32(c[mt][nt], a[mt], b[nt]);
        }
        __syncthreads();
    }

    // epilogue: bias + store (float2 per c-reg pair)
#pragma unroll
    for (int mt = 0; mt < 2; mt++) {
        int m = m0 + wm * 32 + mt * 16 + (lane >> 2);
#pragma unroll
        for (int nt = 0; nt < 8; nt++) {
            int g = n0 + wn * 64 + nt * 8 + (lane & 3) * 2;
            float b0v = g_bcomb[g];
            float b1v = g_bcomb[g + 1];
            float2 o0 = {c[mt][nt][0] + b0v, c[mt][nt][1] + b1v};
            float2 o1 = {c[mt][nt][2] + b0v, c[mt][nt][3] + b1v};
            *reinterpret_cast<float2*>(g_gx + (size_t)m * GALL + g) = o0;
            *reinterpret_cast<float2*>(g_gx + (size_t)(m + 8) * GALL + g) = o1;
        }
    }
}

// ---------------- kernel 2: GRU scan -----------------------------------------
// 512 threads; thread = (u = tid>>2 in 0..127, jb = tid&3 handling 32 j's).
// W_hh in registers as f32x2 pairs; intra-warp shuffle reduction; 1 barrier/step.
__global__ __launch_bounds__(512, 1) void gru_scan(
    const float* __restrict__ Whh_f, const float* __restrict__ bhh_f,
    const float* __restrict__ Whh_b, const float* __restrict__ bhh_b) {
    __shared__ __align__(16) float hbuf[2][HH];

    const int tid = threadIdx.x;
    const int u = tid >> 2;
    const int jb = tid & 3;
    const int blk = blockIdx.x;
    const int n = blk & 63;
    const int dir = blk >> 6;

    const float* Whh = dir ? Whh_b : Whh_f;
    const float* bhh = dir ? bhh_b : bhh_f;
    float* hs_out = dir ? g_hsb : g_hsf;
    const float* gx = g_gx + (size_t)n * TT * GALL + dir * G3;

    const int j0 = jb * 32;
    unsigned long long wr2[16], wz2[16], wn2[16];
#pragma unroll
    for (int q = 0; q < 16; q++) {
        int j = j0 + 2 * q;
        wr2[q] = pack2(Whh[(size_t)u * HH + j], Whh[(size_t)u * HH + j + 1]);
        wz2[q] = pack2(Whh[(size_t)(HH + u) * HH + j], Whh[(size_t)(HH + u) * HH + j + 1]);
        wn2[q] = pack2(Whh[(size_t)(2 * HH + u) * HH + j], Whh[(size_t)(2 * HH + u) * HH + j + 1]);
    }
    const float bhr = bhh[u];
    const float bhz = bhh[HH + u];
    const float bhn = bhh[2 * HH + u];
    float hold = 0.f;
    if (tid < HH) hbuf[0][tid] = 0.f;
    __syncthreads();

    int t = dir ? (TT - 1) : 0;
    const int dt = dir ? -1 : 1;
    int p = 0;

    for (int s = 0; s < TT; s++, t += dt) {
        // prefetch gx for this step (same address in all 4 lanes of a group)
        const float* gxt = gx + (size_t)t * GALL;
        float gxr = __ldcs(gxt + u);
        float gxz = __ldcs(gxt + HH + u);
        float gxn = __ldcs(gxt + 2 * HH + u);

        const ulonglong2* h2 = reinterpret_cast<const ulonglong2*>(&hbuf[p][j0]);
        unsigned long long ar2 = 0ull, az2 = 0ull, an2 = 0ull;
#pragma unroll
        for (int q2 = 0; q2 < 8; q2++) {
            ulonglong2 hv = h2[q2];
            ar2 = fma2(wr2[2 * q2], hv.x, ar2);
            az2 = fma2(wz2[2 * q2], hv.x, az2);
            an2 = fma2(wn2[2 * q2], hv.x, an2);
            ar2 = fma2(wr2[2 * q2 + 1], hv.y, ar2);
            az2 = fma2(wz2[2 * q2 + 1], hv.y, az2);
            an2 = fma2(wn2[2 * q2 + 1], hv.y, an2);
        }
        float2 fr = unpack2(ar2);
        float2 fz = unpack2(az2);
        float2 fn = unpack2(an2);
        float ar = fr.x + fr.y;
        float az = fz.x + fz.y;
        float an = fn.x + fn.y;
        // reduce across the 4 jb-lanes of this u-group
        ar += __shfl_xor_sync(0xffffffffu, ar, 1);
        az += __shfl_xor_sync(0xffffffffu, az, 1);
        an += __shfl_xor_sync(0xffffffffu, an, 1);
        ar += __shfl_xor_sync(0xffffffffu, ar, 2);
        az += __shfl_xor_sync(0xffffffffu, az, 2);
        an += __shfl_xor_sync(0xffffffffu, an, 2);

        float r = sigm_f(gxr + ar + bhr);
        float z = sigm_f(gxz + az + bhz);
        float nn = tanh_f(gxn + r * (an + bhn));
        float hnew = (1.f - z) * nn + z * hold;
        hold = hnew;
        if (jb == 0) {
            hbuf[p ^ 1][u] = hnew;
            hs_out[((size_t)n * TT + t) * HH + u] = hnew;
        }
        p ^= 1;
        __syncthreads();
    }
}

// ---------------- kernel 3: output projection --------------------------------
// Block = 256 threads = 256 rows; c-dimension chunked by 32 with smem staging
// (conflict-free pad 33) so all global loads are coalesced.
__global__ __launch_bounds__(256) void proj_kernel(
    const float* __restrict__ wo, const float* __restrict__ bo,
    float* __restrict__ out) {
    __shared__ float hch[256][33];      // 33.8 KB
    __shared__ float wch[32][BOTTLE];   // 4 KB

    const int tid = threadIdx.x;
    const int m0 = blockIdx.x * 256;

    float acc[BOTTLE];
#pragma unroll
    for (int b = 0; b < BOTTLE; b++) acc[b] = __ldg(bo + b);

    for (int ch = 0; ch < 8; ch++) {
        const int c0 = ch * 32;                         // 0..224
        const float* src = (c0 < HH) ? g_hsf : g_hsb;
        const int ccol0 = (c0 < HH) ? c0 : (c0 - HH);   // column within src row

        // stage 256 rows x 32 cols (coalesced float4 global loads)
#pragma unroll
        for (int l = 0; l < 4; l++) {
            int idx = tid + l * 256;   // 0..1023
            int r = idx >> 2;          // 0..255
            int f4i = idx & 3;         // 0..3 (32 floats = 8 f4? no: 32 floats = 8 float4)
            // 256 rows * 8 f4 = 2048 loads; do 8 per thread instead:
            (void)r; (void)f4i;
        }
        // (re-done properly below: 8 float4 per thread)
#pragma unroll
        for (int l = 0; l < 8; l++) {
            int idx = tid + l * 256;   // 0..2047
            int r = idx >> 3;          // row 0..255
            int f4i = idx & 7;         // 0..7
            float4 v = *reinterpret_cast<const float4*>(
                src + (size_t)(m0 + r) * HH + ccol0 + f4i * 4);
            hch[r][f4i * 4 + 0] = v.x;
            hch[r][f4i * 4 + 1] = v.y;
            hch[r][f4i * 4 + 2] = v.z;
            hch[r][f4i * 4 + 3] = v.w;
        }
        // stage weight chunk: wch[cc][b] = wo[b][c0+cc]
        for (int i = tid; i < 32 * BOTTLE; i += 256) {
            int cc = i >> 5;
            int b = i & 31;
            wch[cc][b] = wo[(size_t)b * EE + c0 + cc];
        }
        __syncthreads();

#pragma unroll 8
        for (int cc = 0; cc < 32; cc++) {
            float v = hch[tid][cc];
            const float4* w4 = reinterpret_cast<const float4*>(wch[cc]);
#pragma unroll
            for (int b4 = 0; b4 < 8; b4++) {
                float4 wv = w4[b4];
                acc[b4 * 4 + 0] += v * wv.x;
                acc[b4 * 4 + 1] += v * wv.y;
                acc[b4 * 4 + 2] += v * wv.z;
                acc[b4 * 4 + 3] += v * wv.w;
            }
        }
        __syncthreads();
    }

    float4* dst = reinterpret_cast<float4*>(out + (size_t)(m0 + tid) * BOTTLE);
#pragma unroll
    for (int b4 = 0; b4 < 8; b4++) {
        float4 o = {acc[b4 * 4 + 0], acc[b4 * 4 + 1],
                    acc[b4 * 4 + 2], acc[b4 * 4 + 3]};
        dst[b4] = o;
    }
}

// ---------------- launch ------------------------------------------------------
extern "C" void kernel_launch(void* const* d_in, const int* in_sizes, int n_in,
                              void* d_out, int out_size) {
    const float* x      = (const float*)d_in[0];
    const float* w_ih_f = (const float*)d_in[1];
    const float* w_hh_f = (const float*)d_in[2];
    const float* b_ih_f = (const float*)d_in[3];
    const float* b_hh_f = (const float*)d_in[4];
    const float* w_ih_b = (const float*)d_in[5];
    const float* w_hh_b = (const float*)d_in[6];
    const float* b_ih_b = (const float*)d_in[7];
    const float* b_hh_b = (const float*)d_in[8];
    const float* w_out  = (const float*)d_in[9];
    const float* b_out  = (const float*)d_in[10];
    float* out = (float*)d_out;

    pack_weights<<<GALL, 256>>>(w_ih_f, b_ih_f, w_ih_b, b_ih_b);
    gemm_gx_mma<<<dim3(MROWS / GBM, GALL / GBN), 256>>>(x);
    gru_scan<<<128, 512>>>(w_hh_f, b_hh_f, w_hh_b, b_hh_b);
    proj_kernel<<<MROWS / 256, 256>>>(w_out, b_out, out);
}

// round 3
// speedup vs baseline: 1.1222x; 1.1222x over previous
#include <cuda_runtime.h>
#include <cuda_bf16.h>
#include <cstdint>

// Problem constants
#define NB   64
#define TT   1024
#define EE   256
#define HH   128
#define G3   384          // 3*H
#define GALL 768          // both directions
#define MROWS (NB*TT)     // 65536
#define BOTTLE 32

// ---------------- scratch (static device globals; no runtime alloc) ----------
__device__ float g_wcomb[GALL * EE];          // [768][256] combined W_ih
__device__ float g_bcomb[GALL];               // [768] combined b_ih
__device__ float g_gx[(size_t)MROWS * GALL];  // [65536][768] input gate preacts
__device__ float g_hsf[(size_t)MROWS * HH];   // forward hidden states  [m][u]
__device__ float g_hsb[(size_t)MROWS * HH];   // backward hidden states [m][u]

// ---------------- helpers ----------------------------------------------------
__device__ __forceinline__ float sigm_f(float x) {
    return __fdividef(1.f, 1.f + __expf(-x));
}
__device__ __forceinline__ float tanh_f(float x) {
    return __fdividef(2.f, 1.f + __expf(-2.f * x)) - 1.f;
}
__device__ __forceinline__ unsigned long long pack2(float lo, float hi) {
    unsigned long long r;
    asm("mov.b64 %0, {%1,%2};" : "=l"(r) : "f"(lo), "f"(hi));
    return r;
}
__device__ __forceinline__ float2 unpack2(unsigned long long v) {
    float2 f;
    asm("mov.b64 {%0,%1}, %2;" : "=f"(f.x), "=f"(f.y) : "l"(v));
    return f;
}
__device__ __forceinline__ unsigned long long fma2(unsigned long long a,
                                                   unsigned long long b,
                                                   unsigned long long c) {
    unsigned long long d;
    asm("fma.rn.f32x2 %0, %1, %2, %3;" : "=l"(d) : "l"(a), "l"(b), "l"(c));
    return d;
}

// ---------------- kernel 0: pack input weights/biases ------------------------
__global__ void pack_weights(const float* __restrict__ w_ih_f,
                             const float* __restrict__ b_ih_f,
                             const float* __restrict__ w_ih_b,
                             const float* __restrict__ b_ih_b) {
    int i = blockIdx.x * blockDim.x + threadIdx.x;
    if (i < GALL * EE) {
        int g = i / EE;
        g_wcomb[i] = (g < G3) ? w_ih_f[i] : w_ih_b[i - G3 * EE];
    }
    if (i < GALL) {
        g_bcomb[i] = (i < G3) ? b_ih_f[i] : b_ih_b[i - G3];
    }
}

// ---------------- kernel 1: gx GEMM  [65536,256] x [256,768], FFMA2 ----------
#define BM 128
#define BN 128
#define BK 32
#define SSTR 132   // padded smem stride (floats); 132*4 % 16 == 0 keeps f4 align
__global__ __launch_bounds__(256) void gemm_gx(const float* __restrict__ X) {
    __shared__ __align__(16) float As[BK][SSTR];
    __shared__ __align__(16) float Bs[BK][SSTR];

    const int m0 = blockIdx.x * BM;
    const int n0 = blockIdx.y * BN;
    const int tid = threadIdx.x;
    const int tx = tid & 15;          // 0..15 -> 8 n-cols
    const int ty = tid >> 4;          // 0..15 -> 8 m-rows

    unsigned long long acc[8][4];     // acc[i][j2] = f32x2 pair of cols (2*j2, 2*j2+1)
#pragma unroll
    for (int i = 0; i < 8; i++)
#pragma unroll
        for (int j = 0; j < 4; j++) acc[i][j] = 0ull;

    for (int k0 = 0; k0 < EE; k0 += BK) {
        // load A tile (128x32) as float4, store transposed As[k][m]
#pragma unroll
        for (int l = 0; l < 4; l++) {
            int lin = tid + l * 256;        // 0..1023
            int r = lin >> 3;               // row 0..127
            int c4 = lin & 7;               // float4 col 0..7
            float4 v = reinterpret_cast<const float4*>(
                X + (size_t)(m0 + r) * EE + k0)[c4];
            As[c4 * 4 + 0][r] = v.x;
            As[c4 * 4 + 1][r] = v.y;
            As[c4 * 4 + 2][r] = v.z;
            As[c4 * 4 + 3][r] = v.w;
        }
        // load B tile (128 n-rows x 32 k) transposed Bs[k][n]
#pragma unroll
        for (int l = 0; l < 4; l++) {
            int lin = tid + l * 256;
            int r = lin >> 3;
            int c4 = lin & 7;
            float4 v = reinterpret_cast<const float4*>(
                g_wcomb + (size_t)(n0 + r) * EE + k0)[c4];
            Bs[c4 * 4 + 0][r] = v.x;
            Bs[c4 * 4 + 1][r] = v.y;
            Bs[c4 * 4 + 2][r] = v.z;
            Bs[c4 * 4 + 3][r] = v.w;
        }
        __syncthreads();

#pragma unroll
        for (int k = 0; k < BK; k++) {
            float4 a0 = *reinterpret_cast<const float4*>(&As[k][ty * 8]);
            float4 a1 = *reinterpret_cast<const float4*>(&As[k][ty * 8 + 4]);
            // b pairs straight from smem as u64 (two consecutive floats)
            ulonglong2 bp0 = *reinterpret_cast<const ulonglong2*>(&Bs[k][tx * 8]);
            ulonglong2 bp1 = *reinterpret_cast<const ulonglong2*>(&Bs[k][tx * 8 + 4]);
            unsigned long long bv[4] = {bp0.x, bp0.y, bp1.x, bp1.y};
            float af[8] = {a0.x, a0.y, a0.z, a0.w, a1.x, a1.y, a1.z, a1.w};
#pragma unroll
            for (int i = 0; i < 8; i++) {
                unsigned long long ap = pack2(af[i], af[i]);
#pragma unroll
                for (int j = 0; j < 4; j++) acc[i][j] = fma2(ap, bv[j], acc[i][j]);
            }
        }
        __syncthreads();
    }

    // epilogue: add bias, store
    unsigned long long bc[4];
#pragma unroll
    for (int j = 0; j < 4; j++)
        bc[j] = *reinterpret_cast<const unsigned long long*>(&g_bcomb[n0 + tx * 8 + j * 2]);

#pragma unroll
    for (int i = 0; i < 8; i++) {
        int m = m0 + ty * 8 + i;
        float* dst = g_gx + (size_t)m * GALL + n0 + tx * 8;
#pragma unroll
        for (int j = 0; j < 4; j++) {
            float2 s = unpack2(acc[i][j]);
            float2 b = unpack2(bc[j]);
            float2 o = {s.x + b.x, s.y + b.y};
            *reinterpret_cast<float2*>(dst + j * 2) = o;
        }
    }
}

// ---------------- kernel 2: GRU scan (1 CTA per (dir, batch) chain) ----------
// 512 threads: thread = (u in 0..127, jb in 0..3); w_hh in registers as f32x2.
__global__ __launch_bounds__(512, 1) void gru_scan(
    const float* __restrict__ Whh_f, const float* __restrict__ bhh_f,
    const float* __restrict__ Whh_b, const float* __restrict__ bhh_b) {
    __shared__ __align__(16) float sh_h[HH];
    __shared__ __align__(16) float sp[4][3][HH];

    const int tid = threadIdx.x;
    const int u = tid & 127;
    const int jb = tid >> 7;          // 0..3, j-range [jb*32, jb*32+32)
    const int blk = blockIdx.x;       // 0..127
    const int n = blk & 63;
    const int dir = blk >> 6;

    const float* Whh = dir ? Whh_b : Whh_f;
    const float* bhh = dir ? bhh_b : bhh_f;
    float* hs_out = dir ? g_hsb : g_hsf;
    const float* gx = g_gx + (size_t)n * TT * GALL + dir * G3;

    // register-resident W_hh slices for this thread's (u, jb), packed as pairs
    const int j0 = jb * 32;
    unsigned long long wr2[16], wz2[16], wn2[16];
#pragma unroll
    for (int q = 0; q < 16; q++) {
        int j = j0 + 2 * q;
        wr2[q] = pack2(Whh[(size_t)u * HH + j], Whh[(size_t)u * HH + j + 1]);
        wz2[q] = pack2(Whh[(size_t)(HH + u) * HH + j], Whh[(size_t)(HH + u) * HH + j + 1]);
        wn2[q] = pack2(Whh[(size_t)(2 * HH + u) * HH + j], Whh[(size_t)(2 * HH + u) * HH + j + 1]);
    }
    float bhr = 0.f, bhz = 0.f, bhn = 0.f, hold = 0.f;
    if (jb == 0) {
        bhr = bhh[u];
        bhz = bhh[HH + u];
        bhn = bhh[2 * HH + u];
        sh_h[u] = 0.f;
    }
    __syncthreads();

    int t = dir ? (TT - 1) : 0;
    const int dt = dir ? -1 : 1;

    for (int s = 0; s < TT; s++, t += dt) {
        // prefetch this step's gx (consumed after the FMA phase -> latency hidden)
        float gxr = 0.f, gxz = 0.f, gxn = 0.f;
        if (jb == 0) {
            const float* gxt = gx + (size_t)t * GALL;
            gxr = __ldcs(gxt + u);
            gxz = __ldcs(gxt + HH + u);
            gxn = __ldcs(gxt + 2 * HH + u);
        }

        // partial matvec over this thread's 32 j's (f32x2 pairs)
        const ulonglong2* h2 = reinterpret_cast<const ulonglong2*>(sh_h + j0);
        unsigned long long ar2 = 0ull, az2 = 0ull, an2 = 0ull;
#pragma unroll
        for (int q2 = 0; q2 < 8; q2++) {
            ulonglong2 hv = h2[q2];
            ar2 = fma2(wr2[2 * q2], hv.x, ar2);
            az2 = fma2(wz2[2 * q2], hv.x, az2);
            an2 = fma2(wn2[2 * q2], hv.x, an2);
            ar2 = fma2(wr2[2 * q2 + 1], hv.y, ar2);
            az2 = fma2(wz2[2 * q2 + 1], hv.y, az2);
            an2 = fma2(wn2[2 * q2 + 1], hv.y, an2);
        }
        float2 fr = unpack2(ar2);
        float2 fz = unpack2(az2);
        float2 fn = unpack2(an2);
        sp[jb][0][u] = fr.x + fr.y;
        sp[jb][1][u] = fz.x + fz.y;
        sp[jb][2][u] = fn.x + fn.y;
        __syncthreads();

        if (jb == 0) {
            float ghr = sp[0][0][u] + sp[1][0][u] + sp[2][0][u] + sp[3][0][u] + bhr;
            float ghz = sp[0][1][u] + sp[1][1][u] + sp[2][1][u] + sp[3][1][u] + bhz;
            float ghn = sp[0][2][u] + sp[1][2][u] + sp[2][2][u] + sp[3][2][u] + bhn;
            float r = sigm_f(gxr + ghr);
            float z = sigm_f(gxz + ghz);
            float nn = tanh_f(gxn + r * ghn);
            float hnew = (1.f - z) * nn + z * hold;
            hold = hnew;
            sh_h[u] = hnew;
            hs_out[((size_t)n * TT + t) * HH + u] = hnew;
        }
        __syncthreads();
    }
}

// ---------------- kernel 3: output projection --------------------------------
// Block = 256 threads = 256 rows; c-dimension chunked by 32 with smem staging.
__global__ __launch_bounds__(256) void proj_kernel(
    const float* __restrict__ wo, const float* __restrict__ bo,
    float* __restrict__ out) {
    __shared__ float hch[256][33];      // 33.8 KB
    __shared__ float wch[32][BOTTLE];   // 4 KB

    const int tid = threadIdx.x;
    const int m0 = blockIdx.x * 256;

    float acc[BOTTLE];
#pragma unroll
    for (int b = 0; b < BOTTLE; b++) acc[b] = __ldg(bo + b);

    for (int ch = 0; ch < 8; ch++) {
        const int c0 = ch * 32;                         // 0..224
        const float* src = (c0 < HH) ? g_hsf : g_hsb;
        const int ccol0 = (c0 < HH) ? c0 : (c0 - HH);

        // stage 256 rows x 32 cols (coalesced float4 global loads)
#pragma unroll
        for (int l = 0; l < 8; l++) {
            int idx = tid + l * 256;   // 0..2047
            int r = idx >> 3;          // row 0..255
            int f4i = idx & 7;         // 0..7
            float4 v = *reinterpret_cast<const float4*>(
                src + (size_t)(m0 + r) * HH + ccol0 + f4i * 4);
            hch[r][f4i * 4 + 0] = v.x;
            hch[r][f4i * 4 + 1] = v.y;
            hch[r][f4i * 4 + 2] = v.z;
            hch[r][f4i * 4 + 3] = v.w;
        }
        // stage weight chunk: wch[cc][b] = wo[b][c0+cc]
        for (int i = tid; i < 32 * BOTTLE; i += 256) {
            int cc = i >> 5;
            int b = i & 31;
            wch[cc][b] = wo[(size_t)b * EE + c0 + cc];
        }
        __syncthreads();

#pragma unroll 8
        for (int cc = 0; cc < 32; cc++) {
            float v = hch[tid][cc];
            const float4* w4 = reinterpret_cast<const float4*>(wch[cc]);
#pragma unroll
            for (int b4 = 0; b4 < 8; b4++) {
                float4 wv = w4[b4];
                acc[b4 * 4 + 0] += v * wv.x;
                acc[b4 * 4 + 1] += v * wv.y;
                acc[b4 * 4 + 2] += v * wv.z;
                acc[b4 * 4 + 3] += v * wv.w;
            }
        }
        __syncthreads();
    }

    float4* dst = reinterpret_cast<float4*>(out + (size_t)(m0 + tid) * BOTTLE);
#pragma unroll
    for (int b4 = 0; b4 < 8; b4++) {
        float4 o = {acc[b4 * 4 + 0], acc[b4 * 4 + 1],
                    acc[b4 * 4 + 2], acc[b4 * 4 + 3]};
        dst[b4] = o;
    }
}

// ---------------- launch ------------------------------------------------------
extern "C" void kernel_launch(void* const* d_in, const int* in_sizes, int n_in,
                              void* d_out, int out_size) {
    const float* x      = (const float*)d_in[0];
    const float* w_ih_f = (const float*)d_in[1];
    const float* w_hh_f = (const float*)d_in[2];
    const float* b_ih_f = (const float*)d_in[3];
    const float* b_hh_f = (const float*)d_in[4];
    const float* w_ih_b = (const float*)d_in[5];
    const float* w_hh_b = (const float*)d_in[6];
    const float* b_ih_b = (const float*)d_in[7];
    const float* b_hh_b = (const float*)d_in[8];
    const float* w_out  = (const float*)d_in[9];
    const float* b_out  = (const float*)d_in[10];
    float* out = (float*)d_out;

    pack_weights<<<GALL, 256>>>(w_ih_f, b_ih_f, w_ih_b, b_ih_b);
    gemm_gx<<<dim3(MROWS / BM, GALL / BN), 256>>>(x);
    gru_scan<<<128, 512>>>(w_hh_f, b_hh_f, w_hh_b, b_hh_b);
    proj_kernel<<<MROWS / 256, 256>>>(w_out, b_out, out);
}

// round 5
// speedup vs baseline: 1.6483x; 1.4688x over previous
#include <cuda_runtime.h>
#include <cuda_bf16.h>
#include <cstdint>

// Problem constants
#define NB   64
#define TT   1024
#define EE   256
#define HH   128
#define G3   384          // 3*H
#define GALL 768          // both directions
#define MROWS (NB*TT)     // 65536
#define BOTTLE 32

// ---------------- scratch (static device globals; no runtime alloc) ----------
__device__ float g_wcomb[GALL * EE];          // [768][256] combined W_ih
__device__ float g_bcomb[GALL];               // [768] combined b_ih
__device__ float g_gx[(size_t)MROWS * GALL];  // [65536][768] input gate preacts
__device__ float g_hsf[(size_t)MROWS * HH];   // forward hidden states  [m][u]
__device__ float g_hsb[(size_t)MROWS * HH];   // backward hidden states [m][u]

// ---------------- helpers ----------------------------------------------------
__device__ __forceinline__ float sigm_f(float x) {
    return __fdividef(1.f, 1.f + __expf(-x));
}
__device__ __forceinline__ float tanh_f(float x) {
    return __fdividef(2.f, 1.f + __expf(-2.f * x)) - 1.f;
}
__device__ __forceinline__ uint32_t cvt_tf32(float f) {
    uint32_t r;
    asm("cvt.rna.tf32.f32 %0, %1;" : "=r"(r) : "f"(f));
    return r;
}
__device__ __forceinline__ void mma_tf32(float* c, const uint32_t* a, const uint32_t* b) {
    asm volatile(
        "mma.sync.aligned.m16n8k8.row.col.f32.tf32.tf32.f32 "
        "{%0,%1,%2,%3}, {%4,%5,%6,%7}, {%8,%9}, {%0,%1,%2,%3};"
        : "+f"(c[0]), "+f"(c[1]), "+f"(c[2]), "+f"(c[3])
        : "r"(a[0]), "r"(a[1]), "r"(a[2]), "r"(a[3]), "r"(b[0]), "r"(b[1]));
}

// ---------------- kernel 0: pack input weights/biases ------------------------
__global__ void pack_weights(const float* __restrict__ w_ih_f,
                             const float* __restrict__ b_ih_f,
                             const float* __restrict__ w_ih_b,
                             const float* __restrict__ b_ih_b) {
    int i = blockIdx.x * blockDim.x + threadIdx.x;
    if (i < GALL * EE) {
        int g = i / EE;
        g_wcomb[i] = (g < G3) ? w_ih_f[i] : w_ih_b[i - G3 * EE];
    }
    if (i < GALL) {
        g_bcomb[i] = (i < G3) ? b_ih_f[i] : b_ih_b[i - G3];
    }
}

// ---------------- kernel 1: gx GEMM via tf32 mma.sync (R2-validated) ----------
// C[65536,768] = X[65536,256] * Wcomb^T[256,768];  tiles 128x128x32, 8 warps.
#define GBM 128
#define GBN 128
#define GBK 32
#define ASTRIDE 136
__global__ __launch_bounds__(256) void gemm_gx_mma(const float* __restrict__ X) {
    __shared__ uint32_t As[GBK][ASTRIDE];   // As[k][m] (tf32 bits)
    __shared__ uint32_t Bs[GBK][ASTRIDE];   // Bs[k][n]

    const int tid = threadIdx.x;
    const int lane = tid & 31;
    const int warp = tid >> 5;
    const int wm = warp & 3;      // 0..3 -> 32-row slab
    const int wn = warp >> 2;     // 0..1 -> 64-col slab
    const int m0 = blockIdx.x * GBM;
    const int n0 = blockIdx.y * GBN;

    float c[2][8][4];
#pragma unroll
    for (int mt = 0; mt < 2; mt++)
#pragma unroll
        for (int nt = 0; nt < 8; nt++)
#pragma unroll
            for (int q = 0; q < 4; q++) c[mt][nt][q] = 0.f;

    for (int k0 = 0; k0 < EE; k0 += GBK) {
        // A tile: X[m0+r][k0+c], stored transposed As[k][m]
#pragma unroll
        for (int l = 0; l < 4; l++) {
            int idx = tid + l * 256;       // 0..1023
            int r = idx >> 3;
            int c4 = idx & 7;
            float4 v = *reinterpret_cast<const float4*>(
                X + (size_t)(m0 + r) * EE + k0 + c4 * 4);
            As[c4 * 4 + 0][r] = cvt_tf32(v.x);
            As[c4 * 4 + 1][r] = cvt_tf32(v.y);
            As[c4 * 4 + 2][r] = cvt_tf32(v.z);
            As[c4 * 4 + 3][r] = cvt_tf32(v.w);
        }
        // B tile: wcomb[n0+r][k0+c] -> Bs[k][n]
#pragma unroll
        for (int l = 0; l < 4; l++) {
            int idx = tid + l * 256;
            int r = idx >> 3;
            int c4 = idx & 7;
            float4 v = *reinterpret_cast<const float4*>(
                g_wcomb + (size_t)(n0 + r) * EE + k0 + c4 * 4);
            Bs[c4 * 4 + 0][r] = cvt_tf32(v.x);
            Bs[c4 * 4 + 1][r] = cvt_tf32(v.y);
            Bs[c4 * 4 + 2][r] = cvt_tf32(v.z);
            Bs[c4 * 4 + 3][r] = cvt_tf32(v.w);
        }
        __syncthreads();

#pragma unroll
        for (int kt = 0; kt < 4; kt++) {
            const int kb = kt * 8;
            uint32_t a[2][4];
            uint32_t b[8][2];
            const int kc = kb + (lane & 3);
#pragma unroll
            for (int mt = 0; mt < 2; mt++) {
                int m = wm * 32 + mt * 16 + (lane >> 2);
                a[mt][0] = As[kc][m];
                a[mt][1] = As[kc][m + 8];
                a[mt][2] = As[kc + 4][m];
                a[mt][3] = As[kc + 4][m + 8];
            }
#pragma unroll
            for (int nt = 0; nt < 8; nt++) {
                int n = wn * 64 + nt * 8 + (lane >> 2);
                b[nt][0] = Bs[kc][n];
                b[nt][1] = Bs[kc + 4][n];
            }
#pragma unroll
            for (int mt = 0; mt < 2; mt++)
#pragma unroll
                for (int nt = 0; nt < 8; nt++) mma_tf32(c[mt][nt], a[mt], b[nt]);
        }
        __syncthreads();
    }

    // epilogue: bias + store (float2 per c-reg pair)
#pragma unroll
    for (int mt = 0; mt < 2; mt++) {
        int m = m0 + wm * 32 + mt * 16 + (lane >> 2);
#pragma unroll
        for (int nt = 0; nt < 8; nt++) {
            int g = n0 + wn * 64 + nt * 8 + (lane & 3) * 2;
            float b0v = g_bcomb[g];
            float b1v = g_bcomb[g + 1];
            float2 o0 = {c[mt][nt][0] + b0v, c[mt][nt][1] + b1v};
            float2 o1 = {c[mt][nt][2] + b0v, c[mt][nt][3] + b1v};
            *reinterpret_cast<float2*>(g_gx + (size_t)m * GALL + g) = o0;
            *reinterpret_cast<float2*>(g_gx + (size_t)(m + 8) * GALL + g) = o1;
        }
    }
}

// ---------------- kernel 2: GRU scan (R1 form, proven) ------------------------
// 512 threads: thread = (u in 0..127, jb in 0..3); w_hh held in registers.
__global__ __launch_bounds__(512, 1) void gru_scan(
    const float* __restrict__ Whh_f, const float* __restrict__ bhh_f,
    const float* __restrict__ Whh_b, const float* __restrict__ bhh_b) {
    __shared__ __align__(16) float sh_h[HH];
    __shared__ __align__(16) float sp[4][3][HH];

    const int tid = threadIdx.x;
    const int u = tid & 127;
    const int jb = tid >> 7;          // 0..3, j-range [jb*32, jb*32+32)
    const int blk = blockIdx.x;       // 0..127
    const int n = blk & 63;
    const int dir = blk >> 6;

    const float* Whh = dir ? Whh_b : Whh_f;
    const float* bhh = dir ? bhh_b : bhh_f;
    float* hs_out = dir ? g_hsb : g_hsf;
    const float* gx = g_gx + (size_t)n * TT * GALL + dir * G3;

    float wr[32], wz[32], wn[32];
#pragma unroll
    for (int q = 0; q < 32; q++) {
        int j = jb * 32 + q;
        wr[q] = Whh[(size_t)u * HH + j];
        wz[q] = Whh[(size_t)(HH + u) * HH + j];
        wn[q] = Whh[(size_t)(2 * HH + u) * HH + j];
    }
    float bhr = 0.f, bhz = 0.f, bhn = 0.f, hold = 0.f;
    if (jb == 0) {
        bhr = bhh[u];
        bhz = bhh[HH + u];
        bhn = bhh[2 * HH + u];
        sh_h[u] = 0.f;
    }
    __syncthreads();

    int t = dir ? (TT - 1) : 0;
    const int dt = dir ? -1 : 1;

    for (int s = 0; s < TT; s++, t += dt) {
        float gxr = 0.f, gxz = 0.f, gxn = 0.f;
        if (jb == 0) {
            const float* gxt = gx + (size_t)t * GALL;
            gxr = __ldcs(gxt + u);
            gxz = __ldcs(gxt + HH + u);
            gxn = __ldcs(gxt + 2 * HH + u);
        }

        float ar = 0.f, az = 0.f, an = 0.f;
        const float4* h4 = reinterpret_cast<const float4*>(sh_h + jb * 32);
#pragma unroll
        for (int q4 = 0; q4 < 8; q4++) {
            float4 hv = h4[q4];
            ar += wr[q4 * 4 + 0] * hv.x; az += wz[q4 * 4 + 0] * hv.x; an += wn[q4 * 4 + 0] * hv.x;
            ar += wr[q4 * 4 + 1] * hv.y; az += wz[q4 * 4 + 1] * hv.y; an += wn[q4 * 4 + 1] * hv.y;
            ar += wr[q4 * 4 + 2] * hv.z; az += wz[q4 * 4 + 2] * hv.z; an += wn[q4 * 4 + 2] * hv.z;
            ar += wr[q4 * 4 + 3] * hv.w; az += wz[q4 * 4 + 3] * hv.w; an += wn[q4 * 4 + 3] * hv.w;
        }
        sp[jb][0][u] = ar;
        sp[jb][1][u] = az;
        sp[jb][2][u] = an;
        __syncthreads();

        if (jb == 0) {
            float ghr = sp[0][0][u] + sp[1][0][u] + sp[2][0][u] + sp[3][0][u] + bhr;
            float ghz = sp[0][1][u] + sp[1][1][u] + sp[2][1][u] + sp[3][1][u] + bhz;
            float ghn = sp[0][2][u] + sp[1][2][u] + sp[2][2][u] + sp[3][2][u] + bhn;
            float r = sigm_f(gxr + ghr);
            float z = sigm_f(gxz + ghz);
            float nn = tanh_f(gxn + r * ghn);
            float hnew = (1.f - z) * nn + z * hold;
            hold = hnew;
            sh_h[u] = hnew;
            hs_out[((size_t)n * TT + t) * HH + u] = hnew;
        }
        __syncthreads();
    }
}

// ---------------- kernel 3: output projection (staged, proven) ----------------
__global__ __launch_bounds__(256) void proj_kernel(
    const float* __restrict__ wo, const float* __restrict__ bo,
    float* __restrict__ out) {
    __shared__ float hch[256][33];      // 33.8 KB
    __shared__ float wch[32][BOTTLE];   // 4 KB

    const int tid = threadIdx.x;
    const int m0 = blockIdx.x * 256;

    float acc[BOTTLE];
#pragma unroll
    for (int b = 0; b < BOTTLE; b++) acc[b] = __ldg(bo + b);

    for (int ch = 0; ch < 8; ch++) {
        const int c0 = ch * 32;                         // 0..224
        const float* src = (c0 < HH) ? g_hsf : g_hsb;
        const int ccol0 = (c0 < HH) ? c0 : (c0 - HH);

        // stage 256 rows x 32 cols (coalesced float4 global loads)
#pragma unroll
        for (int l = 0; l < 8; l++) {
            int idx = tid + l * 256;   // 0..2047
            int r = idx >> 3;          // row 0..255
            int f4i = idx & 7;         // 0..7
            float4 v = *reinterpret_cast<const float4*>(
                src + (size_t)(m0 + r) * HH + ccol0 + f4i * 4);
            hch[r][f4i * 4 + 0] = v.x;
            hch[r][f4i * 4 + 1] = v.y;
            hch[r][f4i * 4 + 2] = v.z;
            hch[r][f4i * 4 + 3] = v.w;
        }
        // stage weight chunk: wch[cc][b] = wo[b][c0+cc]
        for (int i = tid; i < 32 * BOTTLE; i += 256) {
            int cc = i >> 5;
            int b = i & 31;
            wch[cc][b] = wo[(size_t)b * EE + c0 + cc];
        }
        __syncthreads();

#pragma unroll 8
        for (int cc = 0; cc < 32; cc++) {
            float v = hch[tid][cc];
            const float4* w4 = reinterpret_cast<const float4*>(wch[cc]);
#pragma unroll
            for (int b4 = 0; b4 < 8; b4++) {
                float4 wv = w4[b4];
                acc[b4 * 4 + 0] += v * wv.x;
                acc[b4 * 4 + 1] += v * wv.y;
                acc[b4 * 4 + 2] += v * wv.z;
                acc[b4 * 4 + 3] += v * wv.w;
            }
        }
        __syncthreads();
    }

    float4* dst = reinterpret_cast<float4*>(out + (size_t)(m0 + tid) * BOTTLE);
#pragma unroll
    for (int b4 = 0; b4 < 8; b4++) {
        float4 o = {acc[b4 * 4 + 0], acc[b4 * 4 + 1],
                    acc[b4 * 4 + 2], acc[b4 * 4 + 3]};
        dst[b4] = o;
    }
}

// ---------------- launch ------------------------------------------------------
extern "C" void kernel_launch(void* const* d_in, const int* in_sizes, int n_in,
                              void* d_out, int out_size) {
    const float* x      = (const float*)d_in[0];
    const float* w_ih_f = (const float*)d_in[1];
    const float* w_hh_f = (const float*)d_in[2];
    const float* b_ih_f = (const float*)d_in[3];
    const float* b_hh_f = (const float*)d_in[4];
    const float* w_ih_b = (const float*)d_in[5];
    const float* w_hh_b = (const float*)d_in[6];
    const float* b_ih_b = (const float*)d_in[7];
    const float* b_hh_b = (const float*)d_in[8];
    const float* w_out  = (const float*)d_in[9];
    const float* b_out  = (const float*)d_in[10];
    float* out = (float*)d_out;

    pack_weights<<<GALL, 256>>>(w_ih_f, b_ih_f, w_ih_b, b_ih_b);
    gemm_gx_mma<<<dim3(MROWS / GBM, GALL / GBN), 256>>>(x);
    gru_scan<<<128, 512>>>(w_hh_f, b_hh_f, w_hh_b, b_hh_b);
    proj_kernel<<<MROWS / 256, 256>>>(w_out, b_out, out);
}

// round 6
// speedup vs baseline: 1.7912x; 1.0867x over previous
#include <cuda_runtime.h>
#include <cuda_bf16.h>
#include <cstdint>

// Problem constants
#define NB   64
#define TT   1024
#define EE   256
#define HH   128
#define G3   384          // 3*H
#define GALL 768          // both directions
#define MROWS (NB*TT)     // 65536
#define BOTTLE 32

// ---------------- scratch (static device globals; no runtime alloc) ----------
__device__ float g_wcomb[GALL * EE];          // [768][256] combined W_ih (tf32-rna bits)
__device__ float g_bcomb[GALL];               // [768] combined b_ih (full f32)
__device__ float g_xc[(size_t)MROWS * EE];    // x pre-converted to tf32-rna bits
__device__ float g_gx[(size_t)MROWS * GALL];  // [65536][768] input gate preacts
__device__ float g_hsf[(size_t)MROWS * HH];   // forward hidden states  [m][u]
__device__ float g_hsb[(size_t)MROWS * HH];   // backward hidden states [m][u]

// ---------------- helpers ----------------------------------------------------
__device__ __forceinline__ float sigm_f(float x) {
    return __fdividef(1.f, 1.f + __expf(-x));
}
__device__ __forceinline__ float tanh_f(float x) {
    return __fdividef(2.f, 1.f + __expf(-2.f * x)) - 1.f;
}
__device__ __forceinline__ float cvt_tf32_f(float f) {
    uint32_t r;
    asm("cvt.rna.tf32.f32 %0, %1;" : "=r"(r) : "f"(f));
    return __uint_as_float(r);
}
__device__ __forceinline__ void mma_tf32(float* c, const uint32_t* a, const uint32_t* b) {
    asm volatile(
        "mma.sync.aligned.m16n8k8.row.col.f32.tf32.tf32.f32 "
        "{%0,%1,%2,%3}, {%4,%5,%6,%7}, {%8,%9}, {%0,%1,%2,%3};"
        : "+f"(c[0]), "+f"(c[1]), "+f"(c[2]), "+f"(c[3])
        : "r"(a[0]), "r"(a[1]), "r"(a[2]), "r"(a[3]), "r"(b[0]), "r"(b[1]));
}
__device__ __forceinline__ uint32_t smem_u32(const void* p) {
    uint32_t a;
    asm("{ .reg .u64 t; cvta.to.shared.u64 t, %1; cvt.u32.u64 %0, t; }"
        : "=r"(a) : "l"(p));
    return a;
}
__device__ __forceinline__ void cp_async16(uint32_t s, const void* g) {
    asm volatile("cp.async.cg.shared.global [%0], [%1], 16;" :: "r"(s), "l"(g));
}
__device__ __forceinline__ void cp_commit() {
    asm volatile("cp.async.commit_group;");
}

// ---------------- kernel 0a: pack W (tf32-rna) + bias -------------------------
__global__ void pack_weights(const float* __restrict__ w_ih_f,
                             const float* __restrict__ b_ih_f,
                             const float* __restrict__ w_ih_b,
                             const float* __restrict__ b_ih_b) {
    int i = blockIdx.x * blockDim.x + threadIdx.x;
    if (i < GALL * EE) {
        int g = i / EE;
        float v = (g < G3) ? w_ih_f[i] : w_ih_b[i - G3 * EE];
        g_wcomb[i] = cvt_tf32_f(v);
    }
    if (i < GALL) {
        g_bcomb[i] = (i < G3) ? b_ih_f[i] : b_ih_b[i - G3];
    }
}

// ---------------- kernel 0b: pack X (tf32-rna) --------------------------------
__global__ void pack_xc(const float* __restrict__ X) {
    size_t i4 = (size_t)blockIdx.x * blockDim.x + threadIdx.x;
    if (i4 < (size_t)MROWS * EE / 4) {
        float4 v = reinterpret_cast<const float4*>(X)[i4];
        float4 o = {cvt_tf32_f(v.x), cvt_tf32_f(v.y),
                    cvt_tf32_f(v.z), cvt_tf32_f(v.w)};
        reinterpret_cast<float4*>(g_xc)[i4] = o;
    }
}

// ---------------- kernel 1: gx GEMM, tf32 mma + cp.async double buffer --------
// C[65536,768] = Xc @ Wcomb^T.  Tile 128x128, K chunks of 16, 2-stage pipeline.
#define GBM 128
#define GBN 128
#define GBK 16
#define TSTR 20            // smem row stride (floats): (20m+k)%32 all-distinct
#define NK_ITERS (EE / GBK)   // 16
__global__ __launch_bounds__(256, 2) void gemm_gx_mma(void) {
    // 2 stages x (A tile + B tile), each 128 x TSTR floats = 10240 B
    __shared__ __align__(16) float As[2][GBM][TSTR];
    __shared__ __align__(16) float Bs[2][GBN][TSTR];

    const int tid = threadIdx.x;
    const int lane = tid & 31;
    const int warp = tid >> 5;
    const int wm = warp & 3;      // 0..3 -> 32-row slab
    const int wn = warp >> 2;     // 0..1 -> 64-col slab
    const int m0 = blockIdx.x * GBM;
    const int n0 = blockIdx.y * GBN;

    // per-thread cp.async chunk mapping: 4 chunks A + 4 chunks B per stage
    const int lr = tid >> 1;           // row 0..127
    const int lc = (tid & 1) * 2;      // chunk col 0 or 2 (each thread: cols {lc, lc+1})

    float c[2][8][4];
#pragma unroll
    for (int mt = 0; mt < 2; mt++)
#pragma unroll
        for (int nt = 0; nt < 8; nt++)
#pragma unroll
            for (int q = 0; q < 4; q++) c[mt][nt][q] = 0.f;

    const float* gA = g_xc + (size_t)m0 * EE;
    const float* gB = g_wcomb + (size_t)n0 * EE;

    // issue loads for k-chunk `it` into stage s
    auto issue = [&](int it, int s) {
        const int k0 = it * GBK;
#pragma unroll
        for (int cc = 0; cc < 2; cc++) {
            uint32_t sa = smem_u32(&As[s][lr][(lc + cc) * 4]);
            cp_async16(sa, gA + (size_t)lr * EE + k0 + (lc + cc) * 4);
        }
#pragma unroll
        for (int cc = 0; cc < 2; cc++) {
            uint32_t sb = smem_u32(&Bs[s][lr][(lc + cc) * 4]);
            cp_async16(sb, gB + (size_t)lr * EE + k0 + (lc + cc) * 4);
        }
    };

    issue(0, 0);
    cp_commit();

    for (int it = 0; it < NK_ITERS; it++) {
        const int s = it & 1;
        if (it + 1 < NK_ITERS) {
            issue(it + 1, s ^ 1);
            cp_commit();
            asm volatile("cp.async.wait_group 1;");
        } else {
            asm volatile("cp.async.wait_group 0;");
        }
        __syncthreads();

#pragma unroll
        for (int kt = 0; kt < 2; kt++) {
            const int kc = kt * 8 + (lane & 3);
            uint32_t a[2][4];
            uint32_t b[8][2];
#pragma unroll
            for (int mt = 0; mt < 2; mt++) {
                int m = wm * 32 + mt * 16 + (lane >> 2);
                a[mt][0] = __float_as_uint(As[s][m][kc]);
                a[mt][1] = __float_as_uint(As[s][m + 8][kc]);
                a[mt][2] = __float_as_uint(As[s][m][kc + 4]);
                a[mt][3] = __float_as_uint(As[s][m + 8][kc + 4]);
            }
#pragma unroll
            for (int nt = 0; nt < 8; nt++) {
                int n = wn * 64 + nt * 8 + (lane >> 2);
                b[nt][0] = __float_as_uint(Bs[s][n][kc]);
                b[nt][1] = __float_as_uint(Bs[s][n][kc + 4]);
            }
#pragma unroll
            for (int mt = 0; mt < 2; mt++)
#pragma unroll
                for (int nt = 0; nt < 8; nt++) mma_tf32(c[mt][nt], a[mt], b[nt]);
        }
        __syncthreads();
    }

    // epilogue: bias + store
#pragma unroll
    for (int mt = 0; mt < 2; mt++) {
        int m = m0 + wm * 32 + mt * 16 + (lane >> 2);
#pragma unroll
        for (int nt = 0; nt < 8; nt++) {
            int g = n0 + wn * 64 + nt * 8 + (lane & 3) * 2;
            float b0v = g_bcomb[g];
            float b1v = g_bcomb[g + 1];
            float2 o0 = {c[mt][nt][0] + b0v, c[mt][nt][1] + b1v};
            float2 o1 = {c[mt][nt][2] + b0v, c[mt][nt][3] + b1v};
            *reinterpret_cast<float2*>(g_gx + (size_t)m * GALL + g) = o0;
            *reinterpret_cast<float2*>(g_gx + (size_t)(m + 8) * GALL + g) = o1;
        }
    }
}

// ---------------- kernel 2: GRU scan (R1 form, proven) ------------------------
__global__ __launch_bounds__(512, 1) void gru_scan(
    const float* __restrict__ Whh_f, const float* __restrict__ bhh_f,
    const float* __restrict__ Whh_b, const float* __restrict__ bhh_b) {
    __shared__ __align__(16) float sh_h[HH];
    __shared__ __align__(16) float sp[4][3][HH];

    const int tid = threadIdx.x;
    const int u = tid & 127;
    const int jb = tid >> 7;          // 0..3
    const int blk = blockIdx.x;       // 0..127
    const int n = blk & 63;
    const int dir = blk >> 6;

    const float* Whh = dir ? Whh_b : Whh_f;
    const float* bhh = dir ? bhh_b : bhh_f;
    float* hs_out = dir ? g_hsb : g_hsf;
    const float* gx = g_gx + (size_t)n * TT * GALL + dir * G3;

    float wr[32], wz[32], wn[32];
#pragma unroll
    for (int q = 0; q < 32; q++) {
        int j = jb * 32 + q;
        wr[q] = Whh[(size_t)u * HH + j];
        wz[q] = Whh[(size_t)(HH + u) * HH + j];
        wn[q] = Whh[(size_t)(2 * HH + u) * HH + j];
    }
    float bhr = 0.f, bhz = 0.f, bhn = 0.f, hold = 0.f;
    if (jb == 0) {
        bhr = bhh[u];
        bhz = bhh[HH + u];
        bhn = bhh[2 * HH + u];
        sh_h[u] = 0.f;
    }
    __syncthreads();

    int t = dir ? (TT - 1) : 0;
    const int dt = dir ? -1 : 1;

    for (int s = 0; s < TT; s++, t += dt) {
        float gxr = 0.f, gxz = 0.f, gxn = 0.f;
        if (jb == 0) {
            const float* gxt = gx + (size_t)t * GALL;
            gxr = __ldcs(gxt + u);
            gxz = __ldcs(gxt + HH + u);
            gxn = __ldcs(gxt + 2 * HH + u);
        }

        float ar = 0.f, az = 0.f, an = 0.f;
        const float4* h4 = reinterpret_cast<const float4*>(sh_h + jb * 32);
#pragma unroll
        for (int q4 = 0; q4 < 8; q4++) {
            float4 hv = h4[q4];
            ar += wr[q4 * 4 + 0] * hv.x; az += wz[q4 * 4 + 0] * hv.x; an += wn[q4 * 4 + 0] * hv.x;
            ar += wr[q4 * 4 + 1] * hv.y; az += wz[q4 * 4 + 1] * hv.y; an += wn[q4 * 4 + 1] * hv.y;
            ar += wr[q4 * 4 + 2] * hv.z; az += wz[q4 * 4 + 2] * hv.z; an += wn[q4 * 4 + 2] * hv.z;
            ar += wr[q4 * 4 + 3] * hv.w; az += wz[q4 * 4 + 3] * hv.w; an += wn[q4 * 4 + 3] * hv.w;
        }
        sp[jb][0][u] = ar;
        sp[jb][1][u] = az;
        sp[jb][2][u] = an;
        __syncthreads();

        if (jb == 0) {
            float ghr = sp[0][0][u] + sp[1][0][u] + sp[2][0][u] + sp[3][0][u] + bhr;
            float ghz = sp[0][1][u] + sp[1][1][u] + sp[2][1][u] + sp[3][1][u] + bhz;
            float ghn = sp[0][2][u] + sp[1][2][u] + sp[2][2][u] + sp[3][2][u] + bhn;
            float r = sigm_f(gxr + ghr);
            float z = sigm_f(gxz + ghz);
            float nn = tanh_f(gxn + r * ghn);
            float hnew = (1.f - z) * nn + z * hold;
            hold = hnew;
            sh_h[u] = hnew;
            hs_out[((size_t)n * TT + t) * HH + u] = hnew;
        }
        __syncthreads();
    }
}

// ---------------- kernel 3: output projection (staged, proven) ----------------
__global__ __launch_bounds__(256) void proj_kernel(
    const float* __restrict__ wo, const float* __restrict__ bo,
    float* __restrict__ out) {
    __shared__ float hch[256][33];
    __shared__ float wch[32][BOTTLE];

    const int tid = threadIdx.x;
    const int m0 = blockIdx.x * 256;

    float acc[BOTTLE];
#pragma unroll
    for (int b = 0; b < BOTTLE; b++) acc[b] = __ldg(bo + b);

    for (int ch = 0; ch < 8; ch++) {
        const int c0 = ch * 32;
        const float* src = (c0 < HH) ? g_hsf : g_hsb;
        const int ccol0 = (c0 < HH) ? c0 : (c0 - HH);

#pragma unroll
        for (int l = 0; l < 8; l++) {
            int idx = tid + l * 256;
            int r = idx >> 3;
            int f4i = idx & 7;
            float4 v = *reinterpret_cast<const float4*>(
                src + (size_t)(m0 + r) * HH + ccol0 + f4i * 4);
            hch[r][f4i * 4 + 0] = v.x;
            hch[r][f4i * 4 + 1] = v.y;
            hch[r][f4i * 4 + 2] = v.z;
            hch[r][f4i * 4 + 3] = v.w;
        }
        for (int i = tid; i < 32 * BOTTLE; i += 256) {
            int cc = i >> 5;
            int b = i & 31;
            wch[cc][b] = wo[(size_t)b * EE + c0 + cc];
        }
        __syncthreads();

#pragma unroll 8
        for (int cc = 0; cc < 32; cc++) {
            float v = hch[tid][cc];
            const float4* w4 = reinterpret_cast<const float4*>(wch[cc]);
#pragma unroll
            for (int b4 = 0; b4 < 8; b4++) {
                float4 wv = w4[b4];
                acc[b4 * 4 + 0] += v * wv.x;
                acc[b4 * 4 + 1] += v * wv.y;
                acc[b4 * 4 + 2] += v * wv.z;
                acc[b4 * 4 + 3] += v * wv.w;
            }
        }
        __syncthreads();
    }

    float4* dst = reinterpret_cast<float4*>(out + (size_t)(m0 + tid) * BOTTLE);
#pragma unroll
    for (int b4 = 0; b4 < 8; b4++) {
        float4 o = {acc[b4 * 4 + 0], acc[b4 * 4 + 1],
                    acc[b4 * 4 + 2], acc[b4 * 4 + 3]};
        dst[b4] = o;
    }
}

// ---------------- launch ------------------------------------------------------
extern "C" void kernel_launch(void* const* d_in, const int* in_sizes, int n_in,
                              void* d_out, int out_size) {
    const float* x      = (const float*)d_in[0];
    const float* w_ih_f = (const float*)d_in[1];
    const float* w_hh_f = (const float*)d_in[2];
    const float* b_ih_f = (const float*)d_in[3];
    const float* b_hh_f = (const float*)d_in[4];
    const float* w_ih_b = (const float*)d_in[5];
    const float* w_hh_b = (const float*)d_in[6];
    const float* b_ih_b = (const float*)d_in[7];
    const float* b_hh_b = (const float*)d_in[8];
    const float* w_out  = (const float*)d_in[9];
    const float* b_out  = (const float*)d_in[10];
    float* out = (float*)d_out;

    pack_weights<<<GALL, 256>>>(w_ih_f, b_ih_f, w_ih_b, b_ih_b);
    pack_xc<<<MROWS * EE / 4 / 256, 256>>>(x);
    gemm_gx_mma<<<dim3(MROWS / GBM, GALL / GBN), 256>>>();
    gru_scan<<<128, 512>>>(w_hh_f, b_hh_f, w_hh_b, b_hh_b);
    proj_kernel<<<MROWS / 256, 256>>>(w_out, b_out, out);
}